// round 1
// baseline (speedup 1.0000x reference)
#include <cuda_runtime.h>

// QuantumLayer_9483287790225 — analytic closed form.
//
// The reference circuit is:
//   state = |0..0>  (14 qubits, batch 256)
//   per wire i:  RX(pi*x[b,i]) ; RZ(pi*x[b,i])        (angle encoding)
//   per wire i:  RX(weight[0,i])                      (1 entangler layer)
//   CNOT ring: CNOT(0,1), CNOT(1,2), ..., CNOT(13,0)
//   output: <Z_i> for each wire, shape [256, 14]
//
// All single-qubit gates act before any entanglement and the input is |0..0>,
// so the pre-CNOT state is a product state. Per wire:
//   v = RX(w) RZ(b) RX(a) |0>,  a = b = pi*x
//   z := |v0|^2 - |v1|^2 = cos(w)cos(a) - sin(w)sin(a)cos(b)
// The CNOT ring conjugates Z_j into a product of Z's:
//   bit_j(T(s)) = XOR_{k=0..j} b_k (j>=1),  XOR_{k=1..13} b_k (j=0)
// so
//   <Z_0> = prod_{k=1..13} z_k
//   <Z_j> = prod_{k=0..j}  z_k   (j = 1..13)

#define NQ 14
#define BATCH 256

__global__ void quantum_layer_kernel(const float* __restrict__ x,
                                     const float* __restrict__ weight,
                                     float* __restrict__ out)
{
    int b = blockIdx.x * blockDim.x + threadIdx.x;
    if (b >= BATCH) return;

    // Per-wire single-qubit <Z> before the CNOT ring.
    float z[NQ];
#pragma unroll
    for (int i = 0; i < NQ; i++) {
        float xi = x[b * NQ + i];
        float wi = weight[i];
        float sp, cp;                 // sin(pi*x), cos(pi*x)
        sincospif(xi, &sp, &cp);
        float sw, cw;                 // sin(w), cos(w)
        sincosf(wi, &sw, &cw);
        z[i] = cw * cp - sw * sp * cp;
    }

    // <Z_0> = prod z_1..z_13
    float o0 = 1.0f;
#pragma unroll
    for (int k = 1; k < NQ; k++) o0 *= z[k];
    out[b * NQ + 0] = o0;

    // <Z_j> = prod z_0..z_j for j >= 1
    float run = z[0];
#pragma unroll
    for (int j = 1; j < NQ; j++) {
        run *= z[j];
        out[b * NQ + j] = run;
    }
}

extern "C" void kernel_launch(void* const* d_in, const int* in_sizes, int n_in,
                              void* d_out, int out_size)
{
    const float* x      = (const float*)d_in[0];   // [256, 14]
    const float* weight = (const float*)d_in[1];   // [1, 14]
    float* out          = (float*)d_out;           // [256, 14]

    quantum_layer_kernel<<<2, 128>>>(x, weight, out);
}

// round 2
// speedup vs baseline: 1.6173x; 1.6173x over previous
#include <cuda_runtime.h>

// QuantumLayer_9483287790225 — analytic closed form (see R0 derivation).
//
// Pre-CNOT state is a product state; per wire:
//   z_i = cos(w_i)*cos(pi*x_i) - sin(w_i)*sin(pi*x_i)*cos(pi*x_i)
// CNOT ring folds into prefix products:
//   <Z_0> = prod_{k=1..13} z_k ;  <Z_j> = prod_{k=0..j} z_k (j>=1)
//
// R1: libm sincosf/sincospif (~200+ cyc software paths, 28 calls/thread)
// replaced with MUFU __sinf/__cosf; warps spread 1-per-SM to avoid MUFU
// reciprocal-throughput serialization on a single SMSP.

#define NQ 14
#define BATCH 256
#define PI_F 3.14159265358979323846f

__global__ void __launch_bounds__(32, 1)
quantum_layer_kernel(const float* __restrict__ x,
                     const float* __restrict__ weight,
                     float* __restrict__ out)
{
    int b = blockIdx.x * blockDim.x + threadIdx.x;
    if (b >= BATCH) return;

    float z[NQ];
#pragma unroll
    for (int i = 0; i < NQ; i++) {
        float a  = PI_F * x[b * NQ + i];   // in [0, pi)
        float wi = weight[i];              // in [0, 1)
        float sp = __sinf(a);
        float cp = __cosf(a);
        float sw = __sinf(wi);
        float cw = __cosf(wi);
        z[i] = cw * cp - sw * sp * cp;
    }

    // <Z_0> = prod z_1..z_13
    float o0 = 1.0f;
#pragma unroll
    for (int k = 1; k < NQ; k++) o0 *= z[k];
    out[b * NQ + 0] = o0;

    // <Z_j> = prod z_0..z_j for j >= 1
    float run = z[0];
#pragma unroll
    for (int j = 1; j < NQ; j++) {
        run *= z[j];
        out[b * NQ + j] = run;
    }
}

extern "C" void kernel_launch(void* const* d_in, const int* in_sizes, int n_in,
                              void* d_out, int out_size)
{
    const float* x      = (const float*)d_in[0];   // [256, 14]
    const float* weight = (const float*)d_in[1];   // [1, 14]
    float* out          = (float*)d_out;           // [256, 14]

    // 8 blocks x 32 threads: one warp per SM -> no MUFU rt contention.
    quantum_layer_kernel<<<8, 32>>>(x, weight, out);
}

// round 3
// speedup vs baseline: 1.6375x; 1.0125x over previous
#include <cuda_runtime.h>

// QuantumLayer_9483287790225 — analytic closed form (R0 derivation).
//
//   z_i = cos(w_i)*cos(pi*x_i) - sin(w_i)*sin(pi*x_i)*cos(pi*x_i)
//   <Z_0> = z_1*...*z_13 ;  <Z_j> = z_0*...*z_j  (j>=1)
//
// R2: lane-per-wire layout. Each 16-lane subsection handles one batch sample:
// lane i computes z_i (4 MUFU, depth 1), then a 4-step shfl_up product scan
// of v = (i==0 ? 1 : z_i) yields S_j = z_1..z_j. Outputs:
//   <Z_0> = S_13,  <Z_j> = z_0 * S_j.
// Serial critical path drops from ~56 MUFU + 14 load-consumes to
// 4 MUFU + 4 shfl. Two batches per warp; fully coalesced 112B loads/warp.

#define NQ 14
#define BATCH 256
#define PI_F 3.14159265358979323846f

__global__ void __launch_bounds__(128, 1)
quantum_layer_kernel(const float* __restrict__ x,
                     const float* __restrict__ weight,
                     float* __restrict__ out)
{
    const unsigned tid  = blockIdx.x * blockDim.x + threadIdx.x;
    const unsigned lane = threadIdx.x & 31u;
    const unsigned sub  = lane & 15u;           // wire index within subsection
    const unsigned b    = tid >> 4;             // batch = global 16-lane group

    // Load per-wire inputs (lanes with sub >= 14 are padding).
    float xi = 0.0f, wi = 0.0f;
    if (sub < NQ) {
        xi = x[b * NQ + sub];
        wi = weight[sub];
    }

    // z_i = cw*cp - sw*sp*cp
    float a  = PI_F * xi;
    float sp = __sinf(a);
    float cp = __cosf(a);
    float sw = __sinf(wi);
    float cw = __cosf(wi);
    float z  = cw * cp - sw * sp * cp;

    // Scan value: lane 0 contributes 1 so scan yields S_j = z_1..z_j.
    float v = (sub == 0 || sub >= NQ) ? 1.0f : z;

    // Inclusive product scan within each 16-lane subsection.
#pragma unroll
    for (int d = 1; d < 16; d <<= 1) {
        float t = __shfl_up_sync(0xffffffffu, v, d, 16);
        if (sub >= (unsigned)d) v *= t;
    }

    float z0  = __shfl_sync(0xffffffffu, z, 0, 16);    // z_0 of this batch
    float s13 = __shfl_sync(0xffffffffu, v, 13, 16);   // z_1..z_13

    if (sub < NQ) {
        float o = (sub == 0) ? s13 : z0 * v;
        out[b * NQ + sub] = o;
    }
}

extern "C" void kernel_launch(void* const* d_in, const int* in_sizes, int n_in,
                              void* d_out, int out_size)
{
    const float* x      = (const float*)d_in[0];   // [256, 14]
    const float* weight = (const float*)d_in[1];   // [1, 14]
    float* out          = (float*)d_out;           // [256, 14]

    // 256 batches, 2 per warp, 4 warps per block -> 32 blocks x 128 threads.
    quantum_layer_kernel<<<32, 128>>>(x, weight, out);
}